// round 1
// baseline (speedup 1.0000x reference)
#include <cuda_runtime.h>
#include <math.h>
#include <float.h>
#include <stdint.h>

#define BB   8192
#define IND  512
#define DD   256
#define FF   64
#define AA   128
#define NH   8
#define HDIM 16
#define KBUD 16

// ---------------- scratch (static device globals; no allocation) ----------------
__device__ float g_H[(size_t)BB * 384];                 // [B, 384]: relu(ue) | relu(fi) | sd_part(+sd_b1, no relu)
__device__ int   g_cnt[FF];
__device__ int   g_list[(size_t)FF * BB];               // entries: (b<<4)|slot
__device__ float g_enc[(size_t)BB * KBUD * AA];         // [B,16,128]
__device__ float g_qkv[(size_t)BB * KBUD * 3 * AA];     // [B,16,384]
__device__ float g_mctx[(size_t)BB * AA];               // [B,128]
__device__ float g_att[(size_t)BB * AA];                // [B,128]

__global__ void k_init() {
    if (threadIdx.x < FF) g_cnt[threadIdx.x] = 0;
}

// ---------------- K1: fused stage-1 GEMM ----------------
// g_H[b, n] for n<128: relu(x@ue_w1^T + ue_b1); n<256: relu(x@fi_w1^T + fi_b1);
// n<384: x @ sd_w1[:, :512]^T + sd_b1   (relu deferred)
__device__ __forceinline__ const float* k1_wrow(int n, const float* ue_w1,
                                                const float* fi_w1, const float* sd_w1) {
    if (n < AA)     return ue_w1 + (size_t)n * IND;
    if (n < 2 * AA) return fi_w1 + (size_t)(n - AA) * IND;
    return sd_w1 + (size_t)(n - 2 * AA) * (IND + FF);
}

__global__ __launch_bounds__(256) void k_stage1(
    const float* __restrict__ x,
    const float* __restrict__ ue_w1, const float* __restrict__ fi_w1, const float* __restrict__ sd_w1,
    const float* __restrict__ ue_b1, const float* __restrict__ fi_b1, const float* __restrict__ sd_b1)
{
    __shared__ float As[16][128];
    __shared__ float Bs[16][128];
    const int tid  = threadIdx.x;
    const int row0 = blockIdx.y * 128;
    const int col0 = blockIdx.x * 128;
    const int lm = tid >> 2;
    const int lk = (tid & 3) << 2;
    const int tx = tid & 15, ty = tid >> 4;
    const int m0 = ty * 4, n0 = tx * 4;

    float acc[8][8];
#pragma unroll
    for (int i = 0; i < 8; i++)
#pragma unroll
        for (int j = 0; j < 8; j++) acc[i][j] = 0.f;

    const float* w0 = k1_wrow(col0 + lm, ue_w1, fi_w1, sd_w1);
    const float* w1 = k1_wrow(col0 + lm + 64, ue_w1, fi_w1, sd_w1);

    for (int kt = 0; kt < IND; kt += 16) {
        float4 av = *reinterpret_cast<const float4*>(x + (size_t)(row0 + lm) * IND + kt + lk);
        As[lk + 0][lm] = av.x; As[lk + 1][lm] = av.y; As[lk + 2][lm] = av.z; As[lk + 3][lm] = av.w;
        av = *reinterpret_cast<const float4*>(x + (size_t)(row0 + lm + 64) * IND + kt + lk);
        As[lk + 0][lm + 64] = av.x; As[lk + 1][lm + 64] = av.y; As[lk + 2][lm + 64] = av.z; As[lk + 3][lm + 64] = av.w;

        float4 bv = *reinterpret_cast<const float4*>(w0 + kt + lk);
        Bs[lk + 0][lm] = bv.x; Bs[lk + 1][lm] = bv.y; Bs[lk + 2][lm] = bv.z; Bs[lk + 3][lm] = bv.w;
        bv = *reinterpret_cast<const float4*>(w1 + kt + lk);
        Bs[lk + 0][lm + 64] = bv.x; Bs[lk + 1][lm + 64] = bv.y; Bs[lk + 2][lm + 64] = bv.z; Bs[lk + 3][lm + 64] = bv.w;
        __syncthreads();
#pragma unroll
        for (int k = 0; k < 16; k++) {
            float a[8], b[8];
            float4 t0 = *reinterpret_cast<const float4*>(&As[k][m0]);
            float4 t1 = *reinterpret_cast<const float4*>(&As[k][m0 + 64]);
            a[0]=t0.x; a[1]=t0.y; a[2]=t0.z; a[3]=t0.w; a[4]=t1.x; a[5]=t1.y; a[6]=t1.z; a[7]=t1.w;
            float4 u0 = *reinterpret_cast<const float4*>(&Bs[k][n0]);
            float4 u1 = *reinterpret_cast<const float4*>(&Bs[k][n0 + 64]);
            b[0]=u0.x; b[1]=u0.y; b[2]=u0.z; b[3]=u0.w; b[4]=u1.x; b[5]=u1.y; b[6]=u1.z; b[7]=u1.w;
#pragma unroll
            for (int i = 0; i < 8; i++)
#pragma unroll
                for (int j = 0; j < 8; j++) acc[i][j] += a[i] * b[j];
        }
        __syncthreads();
    }

#pragma unroll
    for (int i = 0; i < 8; i++) {
        int m = row0 + m0 + ((i < 4) ? i : 60 + i);
#pragma unroll
        for (int j = 0; j < 8; j++) {
            int n = col0 + n0 + ((j < 4) ? j : 60 + j);
            float v = acc[i][j];
            if (n < AA)          { v += ue_b1[n];          v = fmaxf(v, 0.f); }
            else if (n < 2 * AA) { v += fi_b1[n - AA];     v = fmaxf(v, 0.f); }
            else                 { v += sd_b1[n - 2 * AA]; }
            g_H[(size_t)m * 384 + n] = v;
        }
    }
}

// ---------------- K2: per-row heads, softmax, sigmoid, top-16 selection ----------------
__global__ __launch_bounds__(256) void k_sel(
    const float* __restrict__ ue_w2, const float* __restrict__ ue_b2,
    const float* __restrict__ fi_w2, const float* __restrict__ fi_b2,
    const float* __restrict__ sd_w1, const float* __restrict__ sd_w2, const float* __restrict__ sd_b2,
    const float* __restrict__ costs,
    float* __restrict__ out_unc, float* __restrict__ out_fi, float* __restrict__ out_sp,
    float* __restrict__ out_mask, float* __restrict__ out_sc)
{
    __shared__ float rowH[384];
    __shared__ float red[128];
    __shared__ float fiv[FF];
    __shared__ float h3[AA];
    __shared__ float adj[FF];
    __shared__ int   picked[FF];

    const int t = threadIdx.x;
    const float ueb2 = ue_b2[0];

    for (int r = 0; r < 32; r++) {
        const int b = blockIdx.x * 32 + r;
        for (int i = t; i < 384; i += 256) rowH[i] = g_H[(size_t)b * 384 + i];
        __syncthreads();

        // uncertainty
        if (t < 128) red[t] = ue_w2[t] * rowH[t];
        __syncthreads();
        for (int s = 64; s > 0; s >>= 1) { if (t < s) red[t] += red[t + s]; __syncthreads(); }
        const float uval = (float)(1.0 / (1.0 + exp(-(double)(red[0] + ueb2))));
        if (t == 0) out_unc[b] = uval;
        __syncthreads();

        // feat importance logits + softmax
        if (t < FF) {
            float lg = fi_b2[t];
            const float* wr = fi_w2 + t * AA;
#pragma unroll 8
            for (int a = 0; a < AA; a++) lg += wr[a] * rowH[AA + a];
            fiv[t] = lg; red[t] = lg;
        }
        __syncthreads();
        for (int s = 32; s > 0; s >>= 1) { if (t < s) red[t] = fmaxf(red[t], red[t + s]); __syncthreads(); }
        const float mx = red[0];
        __syncthreads();
        if (t < FF) { float e = (float)exp((double)(fiv[t] - mx)); fiv[t] = e; red[t] = e; }
        __syncthreads();
        for (int s = 32; s > 0; s >>= 1) { if (t < s) red[t] += red[t + s]; __syncthreads(); }
        const float inv = 1.f / red[0];
        __syncthreads();
        if (t < FF) { float p = fiv[t] * inv; fiv[t] = p; out_fi[(size_t)b * FF + t] = p; }
        __syncthreads();

        // sd hidden
        if (t < AA) {
            float v = rowH[2 * AA + t];
            const float* wr = sd_w1 + (size_t)t * (IND + FF) + IND;
#pragma unroll 8
            for (int j = 0; j < FF; j++) v += wr[j] * fiv[j];
            h3[t] = fmaxf(v, 0.f);
        }
        __syncthreads();

        // sampling probs + adjusted
        if (t < FF) {
            float lg = sd_b2[t];
            const float* wr = sd_w2 + t * AA;
#pragma unroll 8
            for (int a = 0; a < AA; a++) lg += wr[a] * h3[a];
            float p = (float)(1.0 / (1.0 + exp(-(double)lg)));
            out_sp[(size_t)b * FF + t] = p;
            adj[t] = p / (1.f + costs[t]) * uval;
            picked[t] = 0;
        }
        __syncthreads();

        // top-16 (warp 0, iterative max with lowest-index tie-break)
        if (t < 32) {
            float csum = 0.f;
            for (int it = 0; it < KBUD; it++) {
                float v0 = picked[t]      ? -FLT_MAX : adj[t];
                float v1 = picked[t + 32] ? -FLT_MAX : adj[t + 32];
                float bvv; int bi;
                if (v1 > v0) { bvv = v1; bi = t + 32; } else { bvv = v0; bi = t; }
#pragma unroll
                for (int off = 16; off; off >>= 1) {
                    float ov = __shfl_down_sync(0xffffffffu, bvv, off);
                    int   oi = __shfl_down_sync(0xffffffffu, bi, off);
                    if (ov > bvv || (ov == bvv && oi < bi)) { bvv = ov; bi = oi; }
                }
                bi = __shfl_sync(0xffffffffu, bi, 0);
                if (t == 0) {
                    picked[bi] = 1;
                    csum += costs[bi];
                    int pos = atomicAdd(&g_cnt[bi], 1);
                    g_list[(size_t)bi * BB + pos] = (b << 4) | it;
                }
                __syncwarp();
            }
            if (t == 0) out_sc[b] = csum;
        }
        __syncthreads();
        if (t < FF) out_mask[(size_t)b * FF + t] = picked[t] ? 1.f : 0.f;
        __syncthreads();
    }
}

// ---------------- K3: grouped gather-encoder GEMM (per feature) ----------------
__global__ __launch_bounds__(256) void k_enc(
    const float* __restrict__ af, const float* __restrict__ enc_w, const float* __restrict__ enc_b)
{
    const int f = blockIdx.y;
    const int cnt = g_cnt[f];
    const int row0 = blockIdx.x * 128;
    if (row0 >= cnt) return;

    __shared__ int   ents[128];
    __shared__ float As[16][128];
    __shared__ float Bs[16][128];

    const int tid = threadIdx.x;
    const int lm = tid >> 2;
    const int lk = (tid & 3) << 2;
    const int tx = tid & 15, ty = tid >> 4;
    const int m0 = ty * 4, n0 = tx * 4;

    if (tid < 128) ents[tid] = (row0 + tid < cnt) ? g_list[(size_t)f * BB + row0 + tid] : -1;
    __syncthreads();

    float acc[8][8];
#pragma unroll
    for (int i = 0; i < 8; i++)
#pragma unroll
        for (int j = 0; j < 8; j++) acc[i][j] = 0.f;

    const float* afbase = af + (size_t)f * BB * DD;
    const float* wbase  = enc_w + (size_t)f * AA * DD;
    const int e0 = ents[lm], e1 = ents[lm + 64];

    for (int kt = 0; kt < DD; kt += 16) {
        float4 av = (e0 >= 0) ? *reinterpret_cast<const float4*>(afbase + (size_t)(e0 >> 4) * DD + kt + lk)
                              : make_float4(0.f, 0.f, 0.f, 0.f);
        As[lk + 0][lm] = av.x; As[lk + 1][lm] = av.y; As[lk + 2][lm] = av.z; As[lk + 3][lm] = av.w;
        av = (e1 >= 0) ? *reinterpret_cast<const float4*>(afbase + (size_t)(e1 >> 4) * DD + kt + lk)
                       : make_float4(0.f, 0.f, 0.f, 0.f);
        As[lk + 0][lm + 64] = av.x; As[lk + 1][lm + 64] = av.y; As[lk + 2][lm + 64] = av.z; As[lk + 3][lm + 64] = av.w;

        float4 bv = *reinterpret_cast<const float4*>(wbase + (size_t)lm * DD + kt + lk);
        Bs[lk + 0][lm] = bv.x; Bs[lk + 1][lm] = bv.y; Bs[lk + 2][lm] = bv.z; Bs[lk + 3][lm] = bv.w;
        bv = *reinterpret_cast<const float4*>(wbase + (size_t)(lm + 64) * DD + kt + lk);
        Bs[lk + 0][lm + 64] = bv.x; Bs[lk + 1][lm + 64] = bv.y; Bs[lk + 2][lm + 64] = bv.z; Bs[lk + 3][lm + 64] = bv.w;
        __syncthreads();
#pragma unroll
        for (int k = 0; k < 16; k++) {
            float a[8], b[8];
            float4 t0 = *reinterpret_cast<const float4*>(&As[k][m0]);
            float4 t1 = *reinterpret_cast<const float4*>(&As[k][m0 + 64]);
            a[0]=t0.x; a[1]=t0.y; a[2]=t0.z; a[3]=t0.w; a[4]=t1.x; a[5]=t1.y; a[6]=t1.z; a[7]=t1.w;
            float4 u0 = *reinterpret_cast<const float4*>(&Bs[k][n0]);
            float4 u1 = *reinterpret_cast<const float4*>(&Bs[k][n0 + 64]);
            b[0]=u0.x; b[1]=u0.y; b[2]=u0.z; b[3]=u0.w; b[4]=u1.x; b[5]=u1.y; b[6]=u1.z; b[7]=u1.w;
#pragma unroll
            for (int i = 0; i < 8; i++)
#pragma unroll
                for (int j = 0; j < 8; j++) acc[i][j] += a[i] * b[j];
        }
        __syncthreads();
    }

#pragma unroll
    for (int i = 0; i < 8; i++) {
        int mi = m0 + ((i < 4) ? i : 60 + i);
        int e = ents[mi];
        if (e < 0) continue;
        float* outr = g_enc + ((size_t)(e >> 4) * KBUD + (e & 15)) * AA;
#pragma unroll
        for (int j = 0; j < 8; j++) {
            int n = n0 + ((j < 4) ? j : 60 + j);
            outr[n] = acc[i][j] + enc_b[f * AA + n];
        }
    }
}

// ---------------- generic tiled GEMM: C = A[M,K] @ W[N,K]^T + bias (+addsrc) ----------------
__global__ __launch_bounds__(256) void k_gemm(
    const float* __restrict__ Am, const float* __restrict__ W,
    const float* __restrict__ bias, const float* __restrict__ addsrc,
    float* __restrict__ C, int M, int N, int K)
{
    __shared__ float As[16][128];
    __shared__ float Bs[16][128];
    const int tid  = threadIdx.x;
    const int row0 = blockIdx.y * 128;
    const int col0 = blockIdx.x * 128;
    const int lm = tid >> 2;
    const int lk = (tid & 3) << 2;
    const int tx = tid & 15, ty = tid >> 4;
    const int m0 = ty * 4, n0 = tx * 4;

    float acc[8][8];
#pragma unroll
    for (int i = 0; i < 8; i++)
#pragma unroll
        for (int j = 0; j < 8; j++) acc[i][j] = 0.f;

    for (int kt = 0; kt < K; kt += 16) {
        float4 av = *reinterpret_cast<const float4*>(Am + (size_t)(row0 + lm) * K + kt + lk);
        As[lk + 0][lm] = av.x; As[lk + 1][lm] = av.y; As[lk + 2][lm] = av.z; As[lk + 3][lm] = av.w;
        av = *reinterpret_cast<const float4*>(Am + (size_t)(row0 + lm + 64) * K + kt + lk);
        As[lk + 0][lm + 64] = av.x; As[lk + 1][lm + 64] = av.y; As[lk + 2][lm + 64] = av.z; As[lk + 3][lm + 64] = av.w;
        float4 bv = *reinterpret_cast<const float4*>(W + (size_t)(col0 + lm) * K + kt + lk);
        Bs[lk + 0][lm] = bv.x; Bs[lk + 1][lm] = bv.y; Bs[lk + 2][lm] = bv.z; Bs[lk + 3][lm] = bv.w;
        bv = *reinterpret_cast<const float4*>(W + (size_t)(col0 + lm + 64) * K + kt + lk);
        Bs[lk + 0][lm + 64] = bv.x; Bs[lk + 1][lm + 64] = bv.y; Bs[lk + 2][lm + 64] = bv.z; Bs[lk + 3][lm + 64] = bv.w;
        __syncthreads();
#pragma unroll
        for (int k = 0; k < 16; k++) {
            float a[8], b[8];
            float4 t0 = *reinterpret_cast<const float4*>(&As[k][m0]);
            float4 t1 = *reinterpret_cast<const float4*>(&As[k][m0 + 64]);
            a[0]=t0.x; a[1]=t0.y; a[2]=t0.z; a[3]=t0.w; a[4]=t1.x; a[5]=t1.y; a[6]=t1.z; a[7]=t1.w;
            float4 u0 = *reinterpret_cast<const float4*>(&Bs[k][n0]);
            float4 u1 = *reinterpret_cast<const float4*>(&Bs[k][n0 + 64]);
            b[0]=u0.x; b[1]=u0.y; b[2]=u0.z; b[3]=u0.w; b[4]=u1.x; b[5]=u1.y; b[6]=u1.z; b[7]=u1.w;
#pragma unroll
            for (int i = 0; i < 8; i++)
#pragma unroll
                for (int j = 0; j < 8; j++) acc[i][j] += a[i] * b[j];
        }
        __syncthreads();
    }

#pragma unroll
    for (int i = 0; i < 8; i++) {
        int m = row0 + m0 + ((i < 4) ? i : 60 + i);
#pragma unroll
        for (int j = 0; j < 8; j++) {
            int n = col0 + n0 + ((j < 4) ? j : 60 + j);
            float v = acc[i][j];
            if (bias)   v += bias[n];
            if (addsrc) v += addsrc[(size_t)m * N + n];
            C[(size_t)m * N + n] = v;
        }
    }
}

// ---------------- K5: compact attention per batch row ----------------
// 16 real rows + phantom row (qkv = in_proj_b) with multiplicity 48.
__global__ __launch_bounds__(256) void k_attn(const float* __restrict__ in_proj_b)
{
    __shared__ float qkvs[KBUD * 384];
    __shared__ float pb[384];
    __shared__ float ctx[17 * AA];

    const int b = blockIdx.x, t = threadIdx.x;
    const float* src = g_qkv + (size_t)b * KBUD * 384;
    for (int i = t; i < KBUD * 384; i += 256) qkvs[i] = src[i];
    for (int i = t; i < 384; i += 256) pb[i] = in_proj_b[i];
    __syncthreads();

    if (t < NH * 17) {
        const int h = t / 17, s = t % 17;
        const float* q = (s < 16) ? (qkvs + s * 384 + h * HDIM) : (pb + h * HDIM);
        float e[17];
        float mxv = -FLT_MAX;
#pragma unroll
        for (int tk = 0; tk < 17; tk++) {
            const float* kk = (tk < 16) ? (qkvs + tk * 384 + AA + h * HDIM) : (pb + AA + h * HDIM);
            float d = 0.f;
#pragma unroll
            for (int c = 0; c < HDIM; c++) d += q[c] * kk[c];
            d *= 0.25f;
            e[tk] = d;
            mxv = fmaxf(mxv, d);
        }
        float den = 0.f;
#pragma unroll
        for (int tk = 0; tk < 17; tk++) {
            e[tk] = expf(e[tk] - mxv);
            den += (tk < 16) ? e[tk] : 48.f * e[tk];
        }
        const float invd = 1.f / den;
#pragma unroll
        for (int c = 0; c < HDIM; c++) {
            float a = 48.f * e[16] * pb[2 * AA + h * HDIM + c];
#pragma unroll
            for (int tk = 0; tk < 16; tk++) a += e[tk] * qkvs[tk * 384 + 2 * AA + h * HDIM + c];
            ctx[s * AA + h * HDIM + c] = a * invd;
        }
    }
    __syncthreads();
    if (t < AA) {
        float m = 48.f * ctx[16 * AA + t];
#pragma unroll
        for (int s = 0; s < 16; s++) m += ctx[s * AA + t];
        g_mctx[(size_t)b * AA + t] = m * (1.f / 64.f);
    }
}

// ---------------- launch ----------------
extern "C" void kernel_launch(void* const* d_in, const int* in_sizes, int n_in,
                              void* d_out, int out_size)
{
    const float* x     = (const float*)d_in[0];
    const float* af    = (const float*)d_in[1];
    const float* costs = (const float*)d_in[2];
    const float* ue_w1 = (const float*)d_in[3];
    const float* ue_b1 = (const float*)d_in[4];
    const float* ue_w2 = (const float*)d_in[5];
    const float* ue_b2 = (const float*)d_in[6];
    const float* fi_w1 = (const float*)d_in[7];
    const float* fi_b1 = (const float*)d_in[8];
    const float* fi_w2 = (const float*)d_in[9];
    const float* fi_b2 = (const float*)d_in[10];
    const float* sd_w1 = (const float*)d_in[11];
    const float* sd_b1 = (const float*)d_in[12];
    const float* sd_w2 = (const float*)d_in[13];
    const float* sd_b2 = (const float*)d_in[14];
    const float* enc_w = (const float*)d_in[15];
    const float* enc_b = (const float*)d_in[16];
    const float* ipw   = (const float*)d_in[17];
    const float* ipb   = (const float*)d_in[18];
    const float* outpw = (const float*)d_in[19];
    const float* outpb = (const float*)d_in[20];
    const float* opw   = (const float*)d_in[21];
    const float* opb   = (const float*)d_in[22];

    float* out    = (float*)d_out;
    float* o_enh  = out;                                 // B*IN
    float* o_unc  = o_enh + (size_t)BB * IND;            // B
    float* o_fi   = o_unc + BB;                          // B*F
    float* o_sp   = o_fi + (size_t)BB * FF;              // B*F
    float* o_mask = o_sp + (size_t)BB * FF;              // B*F
    float* o_sc   = o_mask + (size_t)BB * FF;            // B

    k_init<<<1, 64>>>();

    // K1: [8192,512] x [512,384]
    k_stage1<<<dim3(3, BB / 128), 256>>>(x, ue_w1, fi_w1, sd_w1, ue_b1, fi_b1, sd_b1);

    // K2: per-row heads + selection
    k_sel<<<BB / 32, 256>>>(ue_w2, ue_b2, fi_w2, fi_b2, sd_w1, sd_w2, sd_b2, costs,
                            o_unc, o_fi, o_sp, o_mask, o_sc);

    // K3: grouped encoder over selected (b,f)
    k_enc<<<dim3(BB / 128, FF), 256>>>(af, enc_w, enc_b);

    // K4: QKV [131072,128] x [128,384]
    k_gemm<<<dim3(3, (BB * KBUD) / 128), 256>>>(g_enc, ipw, ipb, nullptr, g_qkv,
                                                BB * KBUD, 3 * AA, AA);

    // K5: attention -> mean ctx
    k_attn<<<BB, 256>>>(ipb);

    // K6: attended = mean_ctx @ out_proj^T + b
    k_gemm<<<dim3(1, BB / 128), 256>>>(g_mctx, outpw, outpb, nullptr, g_att, BB, AA, AA);

    // K7: enhanced = x + attended @ op_w^T + op_b
    k_gemm<<<dim3(4, BB / 128), 256>>>(g_att, opw, opb, x, o_enh, BB, IND, AA);
}

// round 2
// speedup vs baseline: 1.2987x; 1.2987x over previous
#include <cuda_runtime.h>
#include <math.h>
#include <float.h>
#include <stdint.h>

#define BB   8192
#define IND  512
#define DD   256
#define FF   64
#define AA   128
#define NH   8
#define HDIM 16
#define KBUD 16

// ---------------- scratch (static device globals; no allocation) ----------------
__device__ float g_H[(size_t)BB * 384];                 // [B,384]: relu(ue)|relu(fi)|sd_part(+sd_b1)
__device__ int   g_cnt[FF];
__device__ int   g_list[(size_t)FF * BB];               // entries: (b<<4)|slot
__device__ float g_enc[(size_t)BB * KBUD * AA];         // [B,16,128]
__device__ float g_qkv[(size_t)BB * KBUD * 3 * AA];     // [B,16,384]
__device__ float g_mctx[(size_t)BB * AA];               // [B,128]
__device__ float g_fiT[AA * FF];                        // fi_w2 transposed [a][f]
__device__ float g_sd2T[AA * FF];                       // sd_w2 transposed [a][f]
__device__ float g_sd1T[FF * AA];                       // sd_w1[:,512+j] transposed [j][t]
__device__ float g_Wc[IND * AA];                        // opw @ outpw  [512,128]
__device__ float g_bc[IND];                             // opw@outpb + opb

__global__ void k_init() {
    if (threadIdx.x < FF) g_cnt[threadIdx.x] = 0;
}

// ---------------- tiny transposer for selection weights ----------------
__global__ __launch_bounds__(256) void k_transpose(
    const float* __restrict__ fi_w2, const float* __restrict__ sd_w2,
    const float* __restrict__ sd_w1)
{
    int idx = blockIdx.x * 256 + threadIdx.x;
    if (idx < 8192) {
        int f = idx >> 7, a = idx & 127;
        g_fiT[a * FF + f] = fi_w2[idx];
    } else if (idx < 16384) {
        int k = idx - 8192;
        int f = k >> 7, a = k & 127;
        g_sd2T[a * FF + f] = sd_w2[k];
    } else if (idx < 24576) {
        int k = idx - 16384;
        int t = k >> 6, j = k & 63;
        g_sd1T[j * AA + t] = sd_w1[(size_t)t * (IND + FF) + IND + j];
    }
}

// ---------------- k_combine: Wc = opw @ outpw, bc = opw@outpb + opb ----------------
__global__ __launch_bounds__(256) void k_combine(
    const float* __restrict__ opw, const float* __restrict__ outpw,
    const float* __restrict__ outpb, const float* __restrict__ opb)
{
    const int t = threadIdx.x;
    const int i = blockIdx.x * 8 + (t >> 5);      // row of opw / Wc
    const int c0 = (t & 31) * 4;                  // 4 output cols
    float acc0 = 0.f, acc1 = 0.f, acc2 = 0.f, acc3 = 0.f;
#pragma unroll 4
    for (int a = 0; a < AA; a++) {
        float w = opw[(size_t)i * AA + a];
        const float4 v = *reinterpret_cast<const float4*>(outpw + (size_t)a * AA + c0);
        acc0 += w * v.x; acc1 += w * v.y; acc2 += w * v.z; acc3 += w * v.w;
    }
    float* o = g_Wc + (size_t)i * AA + c0;
    o[0] = acc0; o[1] = acc1; o[2] = acc2; o[3] = acc3;
    if (t < 8) {
        int r = blockIdx.x * 8 + t;
        float s = opb[r];
#pragma unroll 4
        for (int a = 0; a < AA; a++) s += outpb[a] * opw[(size_t)r * AA + a];
        g_bc[r] = s;
    }
}

// ---------------- K1: fused stage-1 GEMM ----------------
__device__ __forceinline__ const float* k1_wrow(int n, const float* ue_w1,
                                                const float* fi_w1, const float* sd_w1) {
    if (n < AA)     return ue_w1 + (size_t)n * IND;
    if (n < 2 * AA) return fi_w1 + (size_t)(n - AA) * IND;
    return sd_w1 + (size_t)(n - 2 * AA) * (IND + FF);
}

__global__ __launch_bounds__(256) void k_stage1(
    const float* __restrict__ x,
    const float* __restrict__ ue_w1, const float* __restrict__ fi_w1, const float* __restrict__ sd_w1,
    const float* __restrict__ ue_b1, const float* __restrict__ fi_b1, const float* __restrict__ sd_b1)
{
    __shared__ float As[16][128];
    __shared__ float Bs[16][128];
    const int tid  = threadIdx.x;
    const int row0 = blockIdx.y * 128;
    const int col0 = blockIdx.x * 128;
    const int lm = tid >> 2;
    const int lk = (tid & 3) << 2;
    const int tx = tid & 15, ty = tid >> 4;
    const int m0 = ty * 4, n0 = tx * 4;

    float acc[8][8];
#pragma unroll
    for (int i = 0; i < 8; i++)
#pragma unroll
        for (int j = 0; j < 8; j++) acc[i][j] = 0.f;

    const float* w0 = k1_wrow(col0 + lm, ue_w1, fi_w1, sd_w1);
    const float* w1 = k1_wrow(col0 + lm + 64, ue_w1, fi_w1, sd_w1);

    for (int kt = 0; kt < IND; kt += 16) {
        float4 av = *reinterpret_cast<const float4*>(x + (size_t)(row0 + lm) * IND + kt + lk);
        As[lk + 0][lm] = av.x; As[lk + 1][lm] = av.y; As[lk + 2][lm] = av.z; As[lk + 3][lm] = av.w;
        av = *reinterpret_cast<const float4*>(x + (size_t)(row0 + lm + 64) * IND + kt + lk);
        As[lk + 0][lm + 64] = av.x; As[lk + 1][lm + 64] = av.y; As[lk + 2][lm + 64] = av.z; As[lk + 3][lm + 64] = av.w;

        float4 bv = *reinterpret_cast<const float4*>(w0 + kt + lk);
        Bs[lk + 0][lm] = bv.x; Bs[lk + 1][lm] = bv.y; Bs[lk + 2][lm] = bv.z; Bs[lk + 3][lm] = bv.w;
        bv = *reinterpret_cast<const float4*>(w1 + kt + lk);
        Bs[lk + 0][lm + 64] = bv.x; Bs[lk + 1][lm + 64] = bv.y; Bs[lk + 2][lm + 64] = bv.z; Bs[lk + 3][lm + 64] = bv.w;
        __syncthreads();
#pragma unroll
        for (int k = 0; k < 16; k++) {
            float a[8], b[8];
            float4 t0 = *reinterpret_cast<const float4*>(&As[k][m0]);
            float4 t1 = *reinterpret_cast<const float4*>(&As[k][m0 + 64]);
            a[0]=t0.x; a[1]=t0.y; a[2]=t0.z; a[3]=t0.w; a[4]=t1.x; a[5]=t1.y; a[6]=t1.z; a[7]=t1.w;
            float4 u0 = *reinterpret_cast<const float4*>(&Bs[k][n0]);
            float4 u1 = *reinterpret_cast<const float4*>(&Bs[k][n0 + 64]);
            b[0]=u0.x; b[1]=u0.y; b[2]=u0.z; b[3]=u0.w; b[4]=u1.x; b[5]=u1.y; b[6]=u1.z; b[7]=u1.w;
#pragma unroll
            for (int i = 0; i < 8; i++)
#pragma unroll
                for (int j = 0; j < 8; j++) acc[i][j] += a[i] * b[j];
        }
        __syncthreads();
    }

#pragma unroll
    for (int i = 0; i < 8; i++) {
        int m = row0 + m0 + ((i < 4) ? i : 60 + i);
#pragma unroll
        for (int j = 0; j < 8; j++) {
            int n = col0 + n0 + ((j < 4) ? j : 60 + j);
            float v = acc[i][j];
            if (n < AA)          { v += ue_b1[n];          v = fmaxf(v, 0.f); }
            else if (n < 2 * AA) { v += fi_b1[n - AA];     v = fmaxf(v, 0.f); }
            else                 { v += sd_b1[n - 2 * AA]; }
            g_H[(size_t)m * 384 + n] = v;
        }
    }
}

// ---------------- K2: warp-per-row selection ----------------
__global__ __launch_bounds__(256) void k_sel(
    const float* __restrict__ ue_w2, const float* __restrict__ ue_b2,
    const float* __restrict__ fi_b2, const float* __restrict__ sd_b2,
    const float* __restrict__ costs,
    float* __restrict__ out_unc, float* __restrict__ out_fi, float* __restrict__ out_sp,
    float* __restrict__ out_mask, float* __restrict__ out_sc)
{
    __shared__ float shH[8][384];
    __shared__ float shP[8][64];
    __shared__ float shh3[8][128];

    const int w = threadIdx.x >> 5;
    const int l = threadIdx.x & 31;
    const int b = blockIdx.x * 8 + w;

    // load row of g_H
#pragma unroll
    for (int i = 0; i < 12; i++) shH[w][l + 32 * i] = g_H[(size_t)b * 384 + l + 32 * i];
    __syncwarp();

    // --- uncertainty ---
    float s = 0.f;
#pragma unroll
    for (int i = 0; i < 4; i++) s += ue_w2[l + 32 * i] * shH[w][l + 32 * i];
#pragma unroll
    for (int off = 16; off; off >>= 1) s += __shfl_xor_sync(0xffffffffu, s, off);
    const float uval = (float)(1.0 / (1.0 + exp(-(double)(s + ue_b2[0]))));
    if (l == 0) out_unc[b] = uval;

    // --- feature-importance logits (lane handles f=l and f=l+32) ---
    float lg0 = fi_b2[l], lg1 = fi_b2[l + 32];
#pragma unroll 4
    for (int a = 0; a < AA; a++) {
        const float h = shH[w][AA + a];
        lg0 += g_fiT[a * FF + l]      * h;
        lg1 += g_fiT[a * FF + l + 32] * h;
    }
    float mx = fmaxf(lg0, lg1);
#pragma unroll
    for (int off = 16; off; off >>= 1) mx = fmaxf(mx, __shfl_xor_sync(0xffffffffu, mx, off));
    float e0 = (float)exp((double)(lg0 - mx));
    float e1 = (float)exp((double)(lg1 - mx));
    float sm = e0 + e1;
#pragma unroll
    for (int off = 16; off; off >>= 1) sm += __shfl_xor_sync(0xffffffffu, sm, off);
    const float inv = 1.f / sm;
    const float p0 = e0 * inv, p1 = e1 * inv;
    shP[w][l] = p0; shP[w][l + 32] = p1;
    out_fi[(size_t)b * FF + l] = p0;
    out_fi[(size_t)b * FF + l + 32] = p1;
    __syncwarp();

    // --- sd hidden (lane handles t = l, l+32, l+64, l+96) ---
#pragma unroll
    for (int i = 0; i < 4; i++) {
        const int t = l + 32 * i;
        float v = shH[w][2 * AA + t];
#pragma unroll 4
        for (int j = 0; j < FF; j++) v += g_sd1T[j * AA + t] * shP[w][j];
        shh3[w][t] = fmaxf(v, 0.f);
    }
    __syncwarp();

    // --- sampling probs + adjusted ---
    float a0 = sd_b2[l], a1 = sd_b2[l + 32];
#pragma unroll 4
    for (int c = 0; c < AA; c++) {
        const float h = shh3[w][c];
        a0 += g_sd2T[c * FF + l]      * h;
        a1 += g_sd2T[c * FF + l + 32] * h;
    }
    const float q0 = (float)(1.0 / (1.0 + exp(-(double)a0)));
    const float q1 = (float)(1.0 / (1.0 + exp(-(double)a1)));
    out_sp[(size_t)b * FF + l] = q0;
    out_sp[(size_t)b * FF + l + 32] = q1;
    const float c0 = costs[l], c1 = costs[l + 32];
    const float adj0 = q0 / (1.f + c0) * uval;
    const float adj1 = q1 / (1.f + c1) * uval;

    // --- top-16, no atomics inside loop ---
    bool pk0 = false, pk1 = false;
    int mypick = 0;
#pragma unroll
    for (int it = 0; it < KBUD; it++) {
        float v0 = pk0 ? -FLT_MAX : adj0;
        float v1 = pk1 ? -FLT_MAX : adj1;
        float bv; int bi;
        if (v1 > v0) { bv = v1; bi = l + 32; } else { bv = v0; bi = l; }
#pragma unroll
        for (int off = 16; off; off >>= 1) {
            float ov = __shfl_xor_sync(0xffffffffu, bv, off);
            int   oi = __shfl_xor_sync(0xffffffffu, bi, off);
            if (ov > bv || (ov == bv && oi < bi)) { bv = ov; bi = oi; }
        }
        if (bi == l)      pk0 = true;
        if (bi == l + 32) pk1 = true;
        if (l == it)      mypick = bi;
    }

    out_mask[(size_t)b * FF + l]      = pk0 ? 1.f : 0.f;
    out_mask[(size_t)b * FF + l + 32] = pk1 ? 1.f : 0.f;
    float cs = (pk0 ? c0 : 0.f) + (pk1 ? c1 : 0.f);
#pragma unroll
    for (int off = 16; off; off >>= 1) cs += __shfl_xor_sync(0xffffffffu, cs, off);
    if (l == 0) out_sc[b] = cs;

    // parallel list append (16 distinct features -> race-free across lanes)
    if (l < KBUD) {
        int pos = atomicAdd(&g_cnt[mypick], 1);
        g_list[(size_t)mypick * BB + pos] = (b << 4) | l;
    }
}

// ---------------- K3: grouped gather-encoder GEMM (per feature) ----------------
__global__ __launch_bounds__(256) void k_enc(
    const float* __restrict__ af, const float* __restrict__ enc_w, const float* __restrict__ enc_b)
{
    const int f = blockIdx.y;
    const int cnt = g_cnt[f];
    const int row0 = blockIdx.x * 128;
    if (row0 >= cnt) return;

    __shared__ int   ents[128];
    __shared__ float As[16][128];
    __shared__ float Bs[16][128];

    const int tid = threadIdx.x;
    const int lm = tid >> 2;
    const int lk = (tid & 3) << 2;
    const int tx = tid & 15, ty = tid >> 4;
    const int m0 = ty * 4, n0 = tx * 4;

    if (tid < 128) ents[tid] = (row0 + tid < cnt) ? g_list[(size_t)f * BB + row0 + tid] : -1;
    __syncthreads();

    float acc[8][8];
#pragma unroll
    for (int i = 0; i < 8; i++)
#pragma unroll
        for (int j = 0; j < 8; j++) acc[i][j] = 0.f;

    const float* afbase = af + (size_t)f * BB * DD;
    const float* wbase  = enc_w + (size_t)f * AA * DD;
    const int e0 = ents[lm], e1 = ents[lm + 64];

    for (int kt = 0; kt < DD; kt += 16) {
        float4 av = (e0 >= 0) ? *reinterpret_cast<const float4*>(afbase + (size_t)(e0 >> 4) * DD + kt + lk)
                              : make_float4(0.f, 0.f, 0.f, 0.f);
        As[lk + 0][lm] = av.x; As[lk + 1][lm] = av.y; As[lk + 2][lm] = av.z; As[lk + 3][lm] = av.w;
        av = (e1 >= 0) ? *reinterpret_cast<const float4*>(afbase + (size_t)(e1 >> 4) * DD + kt + lk)
                       : make_float4(0.f, 0.f, 0.f, 0.f);
        As[lk + 0][lm + 64] = av.x; As[lk + 1][lm + 64] = av.y; As[lk + 2][lm + 64] = av.z; As[lk + 3][lm + 64] = av.w;

        float4 bv = *reinterpret_cast<const float4*>(wbase + (size_t)lm * DD + kt + lk);
        Bs[lk + 0][lm] = bv.x; Bs[lk + 1][lm] = bv.y; Bs[lk + 2][lm] = bv.z; Bs[lk + 3][lm] = bv.w;
        bv = *reinterpret_cast<const float4*>(wbase + (size_t)(lm + 64) * DD + kt + lk);
        Bs[lk + 0][lm + 64] = bv.x; Bs[lk + 1][lm + 64] = bv.y; Bs[lk + 2][lm + 64] = bv.z; Bs[lk + 3][lm + 64] = bv.w;
        __syncthreads();
#pragma unroll
        for (int k = 0; k < 16; k++) {
            float a[8], b[8];
            float4 t0 = *reinterpret_cast<const float4*>(&As[k][m0]);
            float4 t1 = *reinterpret_cast<const float4*>(&As[k][m0 + 64]);
            a[0]=t0.x; a[1]=t0.y; a[2]=t0.z; a[3]=t0.w; a[4]=t1.x; a[5]=t1.y; a[6]=t1.z; a[7]=t1.w;
            float4 u0 = *reinterpret_cast<const float4*>(&Bs[k][n0]);
            float4 u1 = *reinterpret_cast<const float4*>(&Bs[k][n0 + 64]);
            b[0]=u0.x; b[1]=u0.y; b[2]=u0.z; b[3]=u0.w; b[4]=u1.x; b[5]=u1.y; b[6]=u1.z; b[7]=u1.w;
#pragma unroll
            for (int i = 0; i < 8; i++)
#pragma unroll
                for (int j = 0; j < 8; j++) acc[i][j] += a[i] * b[j];
        }
        __syncthreads();
    }

#pragma unroll
    for (int i = 0; i < 8; i++) {
        int mi = m0 + ((i < 4) ? i : 60 + i);
        int e = ents[mi];
        if (e < 0) continue;
        float* outr = g_enc + ((size_t)(e >> 4) * KBUD + (e & 15)) * AA;
#pragma unroll
        for (int j = 0; j < 8; j++) {
            int n = n0 + ((j < 4) ? j : 60 + j);
            outr[n] = acc[i][j] + enc_b[f * AA + n];
        }
    }
}

// ---------------- generic tiled GEMM: C = A[M,K] @ W[N,K]^T + bias (+addsrc) ----------------
__global__ __launch_bounds__(256) void k_gemm(
    const float* __restrict__ Am, const float* __restrict__ W,
    const float* __restrict__ bias, const float* __restrict__ addsrc,
    float* __restrict__ C, int M, int N, int K)
{
    __shared__ float As[16][128];
    __shared__ float Bs[16][128];
    const int tid  = threadIdx.x;
    const int row0 = blockIdx.y * 128;
    const int col0 = blockIdx.x * 128;
    const int lm = tid >> 2;
    const int lk = (tid & 3) << 2;
    const int tx = tid & 15, ty = tid >> 4;
    const int m0 = ty * 4, n0 = tx * 4;

    float acc[8][8];
#pragma unroll
    for (int i = 0; i < 8; i++)
#pragma unroll
        for (int j = 0; j < 8; j++) acc[i][j] = 0.f;

    for (int kt = 0; kt < K; kt += 16) {
        float4 av = *reinterpret_cast<const float4*>(Am + (size_t)(row0 + lm) * K + kt + lk);
        As[lk + 0][lm] = av.x; As[lk + 1][lm] = av.y; As[lk + 2][lm] = av.z; As[lk + 3][lm] = av.w;
        av = *reinterpret_cast<const float4*>(Am + (size_t)(row0 + lm + 64) * K + kt + lk);
        As[lk + 0][lm + 64] = av.x; As[lk + 1][lm + 64] = av.y; As[lk + 2][lm + 64] = av.z; As[lk + 3][lm + 64] = av.w;
        float4 bv = *reinterpret_cast<const float4*>(W + (size_t)(col0 + lm) * K + kt + lk);
        Bs[lk + 0][lm] = bv.x; Bs[lk + 1][lm] = bv.y; Bs[lk + 2][lm] = bv.z; Bs[lk + 3][lm] = bv.w;
        bv = *reinterpret_cast<const float4*>(W + (size_t)(col0 + lm + 64) * K + kt + lk);
        Bs[lk + 0][lm + 64] = bv.x; Bs[lk + 1][lm + 64] = bv.y; Bs[lk + 2][lm + 64] = bv.z; Bs[lk + 3][lm + 64] = bv.w;
        __syncthreads();
#pragma unroll
        for (int k = 0; k < 16; k++) {
            float a[8], b[8];
            float4 t0 = *reinterpret_cast<const float4*>(&As[k][m0]);
            float4 t1 = *reinterpret_cast<const float4*>(&As[k][m0 + 64]);
            a[0]=t0.x; a[1]=t0.y; a[2]=t0.z; a[3]=t0.w; a[4]=t1.x; a[5]=t1.y; a[6]=t1.z; a[7]=t1.w;
            float4 u0 = *reinterpret_cast<const float4*>(&Bs[k][n0]);
            float4 u1 = *reinterpret_cast<const float4*>(&Bs[k][n0 + 64]);
            b[0]=u0.x; b[1]=u0.y; b[2]=u0.z; b[3]=u0.w; b[4]=u1.x; b[5]=u1.y; b[6]=u1.z; b[7]=u1.w;
#pragma unroll
            for (int i = 0; i < 8; i++)
#pragma unroll
                for (int j = 0; j < 8; j++) acc[i][j] += a[i] * b[j];
        }
        __syncthreads();
    }

#pragma unroll
    for (int i = 0; i < 8; i++) {
        int m = row0 + m0 + ((i < 4) ? i : 60 + i);
#pragma unroll
        for (int j = 0; j < 8; j++) {
            int n = col0 + n0 + ((j < 4) ? j : 60 + j);
            float v = acc[i][j];
            if (bias)   v += bias[n];
            if (addsrc) v += addsrc[(size_t)m * N + n];
            C[(size_t)m * N + n] = v;
        }
    }
}

// ---------------- K5: compact attention per batch row ----------------
__global__ __launch_bounds__(256) void k_attn(const float* __restrict__ in_proj_b)
{
    __shared__ float qkvs[KBUD * 384];
    __shared__ float pb[384];
    __shared__ float ctx[17 * AA];

    const int b = blockIdx.x, t = threadIdx.x;
    const float* src = g_qkv + (size_t)b * KBUD * 384;
    for (int i = t; i < KBUD * 384; i += 256) qkvs[i] = src[i];
    for (int i = t; i < 384; i += 256) pb[i] = in_proj_b[i];
    __syncthreads();

    if (t < NH * 17) {
        const int h = t / 17, sidx = t % 17;
        const float* q = (sidx < 16) ? (qkvs + sidx * 384 + h * HDIM) : (pb + h * HDIM);
        float e[17];
        float mxv = -FLT_MAX;
#pragma unroll
        for (int tk = 0; tk < 17; tk++) {
            const float* kk = (tk < 16) ? (qkvs + tk * 384 + AA + h * HDIM) : (pb + AA + h * HDIM);
            float d = 0.f;
#pragma unroll
            for (int c = 0; c < HDIM; c++) d += q[c] * kk[c];
            d *= 0.25f;
            e[tk] = d;
            mxv = fmaxf(mxv, d);
        }
        float den = 0.f;
#pragma unroll
        for (int tk = 0; tk < 17; tk++) {
            e[tk] = expf(e[tk] - mxv);
            den += (tk < 16) ? e[tk] : 48.f * e[tk];
        }
        const float invd = 1.f / den;
#pragma unroll
        for (int c = 0; c < HDIM; c++) {
            float a = 48.f * e[16] * pb[2 * AA + h * HDIM + c];
#pragma unroll
            for (int tk = 0; tk < 16; tk++) a += e[tk] * qkvs[tk * 384 + 2 * AA + h * HDIM + c];
            ctx[sidx * AA + h * HDIM + c] = a * invd;
        }
    }
    __syncthreads();
    if (t < AA) {
        float m = 48.f * ctx[16 * AA + t];
#pragma unroll
        for (int sidx = 0; sidx < 16; sidx++) m += ctx[sidx * AA + t];
        g_mctx[(size_t)b * AA + t] = m * (1.f / 64.f);
    }
}

// ---------------- launch ----------------
extern "C" void kernel_launch(void* const* d_in, const int* in_sizes, int n_in,
                              void* d_out, int out_size)
{
    const float* x     = (const float*)d_in[0];
    const float* af    = (const float*)d_in[1];
    const float* costs = (const float*)d_in[2];
    const float* ue_w1 = (const float*)d_in[3];
    const float* ue_b1 = (const float*)d_in[4];
    const float* ue_w2 = (const float*)d_in[5];
    const float* ue_b2 = (const float*)d_in[6];
    const float* fi_w1 = (const float*)d_in[7];
    const float* fi_b1 = (const float*)d_in[8];
    const float* fi_w2 = (const float*)d_in[9];
    const float* fi_b2 = (const float*)d_in[10];
    const float* sd_w1 = (const float*)d_in[11];
    const float* sd_b1 = (const float*)d_in[12];
    const float* sd_w2 = (const float*)d_in[13];
    const float* sd_b2 = (const float*)d_in[14];
    const float* enc_w = (const float*)d_in[15];
    const float* enc_b = (const float*)d_in[16];
    const float* ipw   = (const float*)d_in[17];
    const float* ipb   = (const float*)d_in[18];
    const float* outpw = (const float*)d_in[19];
    const float* outpb = (const float*)d_in[20];
    const float* opw   = (const float*)d_in[21];
    const float* opb   = (const float*)d_in[22];

    float* out    = (float*)d_out;
    float* o_enh  = out;                                 // B*IN
    float* o_unc  = o_enh + (size_t)BB * IND;            // B
    float* o_fi   = o_unc + BB;                          // B*F
    float* o_sp   = o_fi + (size_t)BB * FF;              // B*F
    float* o_mask = o_sp + (size_t)BB * FF;              // B*F
    float* o_sc   = o_mask + (size_t)BB * FF;            // B

    k_init<<<1, 64>>>();
    k_transpose<<<96, 256>>>(fi_w2, sd_w2, sd_w1);
    k_combine<<<64, 256>>>(opw, outpw, outpb, opb);

    // K1: [8192,512] x [512,384]
    k_stage1<<<dim3(3, BB / 128), 256>>>(x, ue_w1, fi_w1, sd_w1, ue_b1, fi_b1, sd_b1);

    // K2: warp-per-row selection
    k_sel<<<BB / 8, 256>>>(ue_w2, ue_b2, fi_b2, sd_b2, costs,
                           o_unc, o_fi, o_sp, o_mask, o_sc);

    // K3: grouped encoder over selected (b,f)
    k_enc<<<dim3(BB / 128, FF), 256>>>(af, enc_w, enc_b);

    // K4: QKV [131072,128] x [128,384]
    k_gemm<<<dim3(3, (BB * KBUD) / 128), 256>>>(g_enc, ipw, ipb, nullptr, g_qkv,
                                                BB * KBUD, 3 * AA, AA);

    // K5: attention -> mean ctx
    k_attn<<<BB, 256>>>(ipb);

    // K6: enhanced = x + mctx @ Wc^T + bc  (out_proj folded into op)
    k_gemm<<<dim3(4, BB / 128), 256>>>(g_mctx, g_Wc, g_bc, x, o_enh, BB, IND, AA);
}